// round 1
// baseline (speedup 1.0000x reference)
#include <cuda_runtime.h>
#include <math.h>

// Problem constants
#define Bsz  4
#define Tsz  4096
#define Dsz  1024
#define Hn   16
#define DIMh 64
#define Ln   8
#define KBn  4
#define Rn   16
#define Sn   128
#define BT   (Bsz*Tsz)      // 16384
#define BHn  (Bsz*Hn)       // 64

// ---------------- scratch (device globals: no allocation allowed) ----------
__device__ float g_Q  [(size_t)BT*Dsz];
__device__ float g_K  [(size_t)BT*Dsz];
__device__ float g_V  [(size_t)BT*Dsz];
__device__ float g_ATT[(size_t)BT*Dsz];
__device__ float g_bK [(size_t)BHn*Sn*DIMh];
__device__ float g_bV [(size_t)BHn*Sn*DIMh];
__device__ float g_bA [(size_t)BHn*Sn];

// ---------------- SGEMM: C[M,N] = A[M,K] @ B[K,N] (*rowscale) (+bias) ------
// 128x128 tile, BK=16, 256 threads, 8x8 micro-tile per thread.
__global__ void __launch_bounds__(256)
sgemm_kernel(const float* __restrict__ A, const float* __restrict__ B,
             float* __restrict__ C, int M, int N, int K,
             const float* __restrict__ rowscale, const float* __restrict__ bias)
{
    __shared__ float As[16][128];
    __shared__ float Bs[16][128];

    const int tid = threadIdx.x;
    const int bx = blockIdx.x;       // N tile
    const int by = blockIdx.y;       // M tile
    const int tx = tid & 15;
    const int ty = tid >> 4;

    const int arow = tid >> 2;            // 0..63
    const int acol = (tid & 3) << 2;      // 0,4,8,12
    const int brow = tid >> 5;            // 0..7
    const int bcol = (tid & 31) << 2;     // 0..124

    const float* Aptr = A + (size_t)(by * 128) * K;
    const float* Bptr = B + bx * 128;

    float acc[8][8];
    #pragma unroll
    for (int i = 0; i < 8; i++)
        #pragma unroll
        for (int j = 0; j < 8; j++) acc[i][j] = 0.f;

    for (int k0 = 0; k0 < K; k0 += 16) {
        float4 a0 = *(const float4*)(Aptr + (size_t)arow        * K + k0 + acol);
        float4 a1 = *(const float4*)(Aptr + (size_t)(arow + 64) * K + k0 + acol);
        float4 b0 = *(const float4*)(Bptr + (size_t)(k0 + brow)     * N + bcol);
        float4 b1 = *(const float4*)(Bptr + (size_t)(k0 + brow + 8) * N + bcol);

        __syncthreads();   // previous compute done before overwriting smem
        As[acol + 0][arow]      = a0.x; As[acol + 1][arow]      = a0.y;
        As[acol + 2][arow]      = a0.z; As[acol + 3][arow]      = a0.w;
        As[acol + 0][arow + 64] = a1.x; As[acol + 1][arow + 64] = a1.y;
        As[acol + 2][arow + 64] = a1.z; As[acol + 3][arow + 64] = a1.w;
        *(float4*)&Bs[brow][bcol]     = b0;
        *(float4*)&Bs[brow + 8][bcol] = b1;
        __syncthreads();

        #pragma unroll
        for (int k = 0; k < 16; k++) {
            float ra[8], rb[8];
            *(float4*)&ra[0] = *(const float4*)&As[k][ty * 8];
            *(float4*)&ra[4] = *(const float4*)&As[k][ty * 8 + 4];
            *(float4*)&rb[0] = *(const float4*)&Bs[k][tx * 8];
            *(float4*)&rb[4] = *(const float4*)&Bs[k][tx * 8 + 4];
            #pragma unroll
            for (int i = 0; i < 8; i++)
                #pragma unroll
                for (int j = 0; j < 8; j++)
                    acc[i][j] += ra[i] * rb[j];
        }
    }

    #pragma unroll
    for (int i = 0; i < 8; i++) {
        int row = by * 128 + ty * 8 + i;
        float rs = rowscale ? rowscale[row] : 1.0f;
        #pragma unroll
        for (int j = 0; j < 8; j += 4) {
            int col = bx * 128 + tx * 8 + j;
            float4 c;
            c.x = acc[i][j + 0] * rs;
            c.y = acc[i][j + 1] * rs;
            c.z = acc[i][j + 2] * rs;
            c.w = acc[i][j + 3] * rs;
            if (bias) {
                c.x += bias[col + 0]; c.y += bias[col + 1];
                c.z += bias[col + 2]; c.w += bias[col + 3];
            }
            *(float4*)&C[(size_t)row * N + col] = c;
        }
    }
}

// ---------------- zero bucket accumulators (must re-zero every replay) -----
__global__ void zero_buckets(float* __restrict__ bK, float* __restrict__ bV,
                             float* __restrict__ bA)
{
    int n = BHn * Sn * DIMh;
    for (int i = blockIdx.x * blockDim.x + threadIdx.x; i < n;
         i += gridDim.x * blockDim.x) { bK[i] = 0.f; bV[i] = 0.f; }
    int na = BHn * Sn;
    for (int i = blockIdx.x * blockDim.x + threadIdx.x; i < na;
         i += gridDim.x * blockDim.x) bA[i] = 0.f;
}

// ---------------- routing + bucket accumulation ----------------------------
#define RT_TPC    512
#define RT_CHUNKS (Tsz / RT_TPC)    // 8
#define RT_SMEM   ((2*Sn*65 + Sn + DIMh*32 + KBn*Rn) * sizeof(float))

__global__ void route_kernel(const float* __restrict__ K, const float* __restrict__ V,
                             const float* __restrict__ planes_T,
                             const float* __restrict__ protos_T,
                             const float* __restrict__ ltemp,
                             float* __restrict__ bK, float* __restrict__ bV,
                             float* __restrict__ bA)
{
    extern __shared__ float sm[];
    float* sbK = sm;                         // 128*65
    float* sbV = sbK + Sn * 65;              // 128*65
    float* sA  = sbV + Sn * 65;              // 128
    float* spl = sA + Sn;                    // 64*32
    float* spr = spl + DIMh * 32;            // 4*16

    const int tid   = threadIdx.x;
    const int bh    = blockIdx.x / RT_CHUNKS;
    const int chunk = blockIdx.x % RT_CHUNKS;
    const int b = bh / Hn, h = bh % Hn;

    for (int i = tid; i < Sn * 65; i += blockDim.x) { sbK[i] = 0.f; sbV[i] = 0.f; }
    for (int i = tid; i < Sn; i += blockDim.x) sA[i] = 0.f;
    for (int i = tid; i < DIMh * 32; i += blockDim.x) spl[i] = planes_T[i];
    for (int i = tid; i < KBn * Rn; i += blockDim.x) spr[i] = protos_T[i];
    __syncthreads();

    float scale = expf(ltemp[0]);
    scale = fminf(fmaxf(scale, 0.01f), 20.0f);
    const float inv_scale = 1.0f / scale;

    const int t0 = chunk * RT_TPC;
    for (int t = t0 + tid; t < t0 + RT_TPC; t += blockDim.x) {
        const float* krow = K + ((size_t)(b * Tsz + t)) * Dsz + h * DIMh;
        const float* vrow = V + ((size_t)(b * Tsz + t)) * Dsz + h * DIMh;

        float proj[32];
        #pragma unroll
        for (int p = 0; p < 32; p++) proj[p] = 0.f;
        #pragma unroll 4
        for (int d = 0; d < DIMh; d++) {
            float kd = krow[d];
            #pragma unroll
            for (int p = 0; p < 32; p++) proj[p] += kd * spl[d * 32 + p];
        }
        #pragma unroll
        for (int p = 0; p < 32; p++) proj[p] = tanhf(proj[p]) * inv_scale;

        int ss[16]; float ws[16];
        #pragma unroll
        for (int l = 0; l < Ln; l++) {
            float e[16];
            float mx = -1e30f;
            #pragma unroll
            for (int r = 0; r < Rn; r++) {
                float lg = proj[l*4+0] * spr[0*Rn + r] + proj[l*4+1] * spr[1*Rn + r]
                         + proj[l*4+2] * spr[2*Rn + r] + proj[l*4+3] * spr[3*Rn + r];
                e[r] = lg;
                mx = fmaxf(mx, lg);
            }
            float Z = 0.f;
            #pragma unroll
            for (int r = 0; r < Rn; r++) { e[r] = expf(e[r] - mx); Z += e[r]; }
            int i1 = 0; float b1 = e[0];
            #pragma unroll
            for (int r = 1; r < Rn; r++) if (e[r] > b1) { b1 = e[r]; i1 = r; }
            int i2 = -1; float b2 = -1.f;
            #pragma unroll
            for (int r = 0; r < Rn; r++) if (r != i1 && e[r] > b2) { b2 = e[r]; i2 = r; }
            // w = p / (p1 + p2 + 1e-6) with p = e/Z  ->  e / (e1 + e2 + 1e-6*Z)
            float denom = 1.0f / (b1 + b2 + 1e-6f * Z);
            ss[l*2 + 0] = l * Rn + i1; ws[l*2 + 0] = b1 * denom;
            ss[l*2 + 1] = l * Rn + i2; ws[l*2 + 1] = b2 * denom;
        }

        #pragma unroll 2
        for (int d = 0; d < DIMh; d++) {
            float kd = krow[d], vd = vrow[d];
            #pragma unroll
            for (int j = 0; j < 16; j++) {
                atomicAdd(&sbK[ss[j] * 65 + d], ws[j] * kd);
                atomicAdd(&sbV[ss[j] * 65 + d], ws[j] * vd);
            }
        }
        #pragma unroll
        for (int j = 0; j < 16; j++) atomicAdd(&sA[ss[j]], ws[j]);
    }
    __syncthreads();

    const size_t base = (size_t)bh * Sn * DIMh;
    for (int i = tid; i < Sn * DIMh; i += blockDim.x) {
        int s = i / DIMh, d = i % DIMh;
        atomicAdd(&bK[base + i], sbK[s * 65 + d]);
        atomicAdd(&bV[base + i], sbV[s * 65 + d]);
    }
    for (int s = tid; s < Sn; s += blockDim.x)
        atomicAdd(&bA[(size_t)bh * Sn + s], sA[s]);
}

// ---------------- bucket attention (warp per token) ------------------------
#define AT_TPC    512
#define AT_CHUNKS (Tsz / AT_TPC)    // 8
#define AT_SMEM   ((2*Sn*65 + 8*Sn) * sizeof(float))

__global__ void __launch_bounds__(256)
attn_kernel(const float* __restrict__ Q,
            const float* __restrict__ bK, const float* __restrict__ bV,
            const float* __restrict__ bA, float* __restrict__ outp)
{
    extern __shared__ float sm[];
    float* sK = sm;                 // 128*65 (normalized bucket K)
    float* sV = sK + Sn * 65;       // 128*65 (normalized bucket V)
    float* sp = sV + Sn * 65;       // 8 warps * 128 probs

    const int tid   = threadIdx.x;
    const int bh    = blockIdx.x / AT_CHUNKS;
    const int chunk = blockIdx.x % AT_CHUNKS;
    const int b = bh / Hn, h = bh % Hn;

    const size_t base = (size_t)bh * Sn * DIMh;
    for (int i = tid; i < Sn * DIMh; i += blockDim.x) {
        int s = i / DIMh, d = i % DIMh;
        float inv = 1.0f / (bA[(size_t)bh * Sn + s] + 1e-6f);
        sK[s * 65 + d] = bK[base + i] * inv;
        sV[s * 65 + d] = bV[base + i] * inv;
    }
    __syncthreads();

    const int warp = tid >> 5, lane = tid & 31;
    float* pwarp = sp + warp * Sn;

    for (int tt = warp; tt < AT_TPC; tt += 8) {
        const int t = chunk * AT_TPC + tt;
        const float* qrow = Q + ((size_t)(b * Tsz + t)) * Dsz + h * DIMh;
        float q0 = qrow[lane], q1 = qrow[lane + 32];

        float a0 = 0.f, a1 = 0.f, a2 = 0.f, a3 = 0.f;
        #pragma unroll
        for (int d = 0; d < 32; d++) {
            float qd = __shfl_sync(0xffffffffu, q0, d);
            a0 += qd * sK[(lane      ) * 65 + d];
            a1 += qd * sK[(lane + 32 ) * 65 + d];
            a2 += qd * sK[(lane + 64 ) * 65 + d];
            a3 += qd * sK[(lane + 96 ) * 65 + d];
        }
        #pragma unroll
        for (int d = 0; d < 32; d++) {
            float qd = __shfl_sync(0xffffffffu, q1, d);
            a0 += qd * sK[(lane      ) * 65 + 32 + d];
            a1 += qd * sK[(lane + 32 ) * 65 + 32 + d];
            a2 += qd * sK[(lane + 64 ) * 65 + 32 + d];
            a3 += qd * sK[(lane + 96 ) * 65 + 32 + d];
        }
        const float sc = 0.125f;   // 1/sqrt(64)
        a0 *= sc; a1 *= sc; a2 *= sc; a3 *= sc;

        float lm = fmaxf(fmaxf(a0, a1), fmaxf(a2, a3));
        #pragma unroll
        for (int o = 16; o; o >>= 1) lm = fmaxf(lm, __shfl_xor_sync(0xffffffffu, lm, o));
        float e0 = expf(a0 - lm), e1 = expf(a1 - lm), e2 = expf(a2 - lm), e3 = expf(a3 - lm);
        float z = e0 + e1 + e2 + e3;
        #pragma unroll
        for (int o = 16; o; o >>= 1) z += __shfl_xor_sync(0xffffffffu, z, o);
        float invz = 1.0f / z;

        pwarp[lane]      = e0 * invz;
        pwarp[lane + 32] = e1 * invz;
        pwarp[lane + 64] = e2 * invz;
        pwarp[lane + 96] = e3 * invz;
        __syncwarp();

        float o0 = 0.f, o1 = 0.f;
        #pragma unroll 8
        for (int s = 0; s < Sn; s++) {
            float p = pwarp[s];
            o0 += p * sV[s * 65 + lane];
            o1 += p * sV[s * 65 + lane + 32];
        }
        size_t obase = ((size_t)(b * Tsz + t)) * Dsz + h * DIMh;
        outp[obase + lane]      = o0;
        outp[obase + lane + 32] = o1;
        __syncwarp();   // protect pwarp before next iteration's writes
    }
}

// ---------------- launch ----------------------------------------------------
extern "C" void kernel_launch(void* const* d_in, const int* in_sizes, int n_in,
                              void* d_out, int out_size)
{
    const float* x      = (const float*)d_in[0];
    const float* mask   = (const float*)d_in[1];
    const float* Wq     = (const float*)d_in[2];
    const float* Wk     = (const float*)d_in[3];
    const float* Wv     = (const float*)d_in[4];
    const float* Wout   = (const float*)d_in[5];
    const float* b_out  = (const float*)d_in[6];
    const float* planes = (const float*)d_in[7];
    const float* protos = (const float*)d_in[8];
    const float* ltemp  = (const float*)d_in[9];
    float* out = (float*)d_out;

    void *pQ, *pK, *pV, *pATT, *pbK, *pbV, *pbA;
    cudaGetSymbolAddress(&pQ,  g_Q);
    cudaGetSymbolAddress(&pK,  g_K);
    cudaGetSymbolAddress(&pV,  g_V);
    cudaGetSymbolAddress(&pATT,g_ATT);
    cudaGetSymbolAddress(&pbK, g_bK);
    cudaGetSymbolAddress(&pbV, g_bV);
    cudaGetSymbolAddress(&pbA, g_bA);

    cudaFuncSetAttribute(route_kernel, cudaFuncAttributeMaxDynamicSharedMemorySize, RT_SMEM);
    cudaFuncSetAttribute(attn_kernel,  cudaFuncAttributeMaxDynamicSharedMemorySize, AT_SMEM);

    dim3 gblk(256);
    dim3 ggrid(Dsz / 128, BT / 128);   // (8, 128)

    // Q/K/V projections with mask folded in as per-row scale
    sgemm_kernel<<<ggrid, gblk>>>(x, Wq, (float*)pQ, BT, Dsz, Dsz, mask, nullptr);
    sgemm_kernel<<<ggrid, gblk>>>(x, Wk, (float*)pK, BT, Dsz, Dsz, mask, nullptr);
    sgemm_kernel<<<ggrid, gblk>>>(x, Wv, (float*)pV, BT, Dsz, Dsz, mask, nullptr);

    // bucket accumulation
    zero_buckets<<<256, 256>>>((float*)pbK, (float*)pbV, (float*)pbA);
    route_kernel<<<BHn * RT_CHUNKS, 256, RT_SMEM>>>(
        (const float*)pK, (const float*)pV, planes, protos, ltemp,
        (float*)pbK, (float*)pbV, (float*)pbA);

    // bucket attention
    attn_kernel<<<BHn * AT_CHUNKS, 256, AT_SMEM>>>(
        (const float*)pQ, (const float*)pbK, (const float*)pbV, (const float*)pbA,
        (float*)pATT);

    // output projection with bias
    sgemm_kernel<<<ggrid, gblk>>>((const float*)pATT, Wout, out, BT, Dsz, Dsz,
                                  nullptr, b_out);
}